// round 3
// baseline (speedup 1.0000x reference)
#include <cuda_runtime.h>
#include <cuda_bf16.h>
#include <math.h>

#define N_VIEWS   512
#define N_MULTI   32
#define MAX_SIFT  2048
#define N_MATCHES 1000000

#define FEAT_ELEMS (N_VIEWS * MAX_SIFT * 3)   // 3,145,728
#define FLAT_ROWS  (N_VIEWS * MAX_SIFT)       // 1,048,576

// Scratch for the per-view cumulative rotation (row-major 3x3) and translation.
__device__ float g_c33[N_VIEWS * 9];
__device__ float g_c3[N_VIEWS * 3];

// ---------------------------------------------------------------------------
// Kernel 1: build rotations + Kogge-Stone prefix matmul scan + cumsum(c_3).
// One block of 512 threads (one thread per view).
// ---------------------------------------------------------------------------
__global__ void scan_kernel(const float* __restrict__ euler,   // (512,3)
                            const float* __restrict__ c_3)     // (512,1,3)
{
    __shared__ float M[N_VIEWS][9];
    __shared__ float T[N_VIEWS][3];

    const int i = threadIdx.x;   // view index, blockDim.x == 512

    // Build rotation from Tait-Bryan angles
    float a = euler[i * 3 + 0];
    float b = euler[i * 3 + 1];
    float c = euler[i * 3 + 2];
    float sa, ca, sb, cb, sc, cc;
    sincosf(a, &sa, &ca);
    sincosf(b, &sb, &cb);
    sincosf(c, &sc, &cc);

    M[i][0] = ca * cc + sa * sb * sc;
    M[i][1] = -sa * cb;
    M[i][2] = -ca * sc + sa * sb * cc;
    M[i][3] = sa * cc - ca * sb * sc;
    M[i][4] = ca * cb;
    M[i][5] = -sa * sc - ca * sb * cc;
    M[i][6] = cb * sc;
    M[i][7] = sb;
    M[i][8] = cb * cc;

    T[i][0] = c_3[i * 3 + 0];
    T[i][1] = c_3[i * 3 + 1];
    T[i][2] = c_3[i * 3 + 2];

    __syncthreads();

    // Kogge-Stone inclusive scan: P[i] = rot0 @ rot1 @ ... @ rot_i
    // Update rule (non-commutative, left operand is the earlier prefix):
    //   P_new[i] = P_old[i-d] @ P_old[i]
    #pragma unroll
    for (int d = 1; d < N_VIEWS; d <<= 1) {
        float A[9], B[9];
        float t0 = 0.f, t1 = 0.f, t2 = 0.f;
        #pragma unroll
        for (int k = 0; k < 9; k++) { A[k] = 0.f; B[k] = 0.f; }
        const bool active = (i >= d);
        if (active) {
            #pragma unroll
            for (int k = 0; k < 9; k++) { A[k] = M[i - d][k]; B[k] = M[i][k]; }
            t0 = T[i - d][0]; t1 = T[i - d][1]; t2 = T[i - d][2];
        }
        __syncthreads();
        if (active) {
            #pragma unroll
            for (int r = 0; r < 3; r++)
                #pragma unroll
                for (int cc2 = 0; cc2 < 3; cc2++) {
                    float s = A[r * 3 + 0] * B[0 * 3 + cc2]
                            + A[r * 3 + 1] * B[1 * 3 + cc2]
                            + A[r * 3 + 2] * B[2 * 3 + cc2];
                    M[i][r * 3 + cc2] = s;
                }
            T[i][0] += t0; T[i][1] += t1; T[i][2] += t2;
        }
        __syncthreads();
    }

    #pragma unroll
    for (int k = 0; k < 9; k++) g_c33[i * 9 + k] = M[i][k];
    g_c3[i * 3 + 0] = T[i][0];
    g_c3[i * 3 + 1] = T[i][1];
    g_c3[i * 3 + 2] = T[i][2];
}

// ---------------------------------------------------------------------------
// Kernel 2: feat[v,s,:] = (sum_m beta[v,m]*pdepth[v,:,m,s] + pdepth0[v,:,s]) @ c33[v] + c3[v]
// One block per view, 512 threads, each thread handles one float4 (4 sifts).
// ---------------------------------------------------------------------------
__global__ void __launch_bounds__(512)
feat_kernel(const float* __restrict__ beta,      // (512,1,1,32)
            const float* __restrict__ pdepth,    // (512,3,32,2048)
            const float* __restrict__ pdepth0,   // (512,3,1,2048)
            float* __restrict__ feat)            // (512,2048,3)
{
    const int v = blockIdx.x;
    const int q = threadIdx.x;   // quad index: sifts [4q, 4q+3]

    __shared__ float sb[N_MULTI];
    __shared__ float sR[9];
    __shared__ float sT[3];

    if (threadIdx.x < N_MULTI) sb[threadIdx.x] = beta[v * N_MULTI + threadIdx.x];
    if (threadIdx.x >= 64 && threadIdx.x < 73) sR[threadIdx.x - 64] = g_c33[v * 9 + (threadIdx.x - 64)];
    if (threadIdx.x >= 96 && threadIdx.x < 99) sT[threadIdx.x - 96] = g_c3[v * 3 + (threadIdx.x - 96)];
    __syncthreads();

    // accumulators per channel (x,y,z), 4 sifts wide
    const float4* p0 = (const float4*)(pdepth0 + (size_t)v * 3 * MAX_SIFT);
    float4 acc[3];
    #pragma unroll
    for (int ch = 0; ch < 3; ch++)
        acc[ch] = p0[(size_t)ch * (MAX_SIFT / 4) + q];

    const float4* pd = (const float4*)(pdepth + (size_t)v * 3 * N_MULTI * MAX_SIFT);
    #pragma unroll
    for (int m = 0; m < N_MULTI; m++) {
        float bm = sb[m];
        #pragma unroll
        for (int ch = 0; ch < 3; ch++) {
            float4 p = pd[((size_t)ch * N_MULTI + m) * (MAX_SIFT / 4) + q];
            acc[ch].x = fmaf(bm, p.x, acc[ch].x);
            acc[ch].y = fmaf(bm, p.y, acc[ch].y);
            acc[ch].z = fmaf(bm, p.z, acc[ch].z);
            acc[ch].w = fmaf(bm, p.w, acc[ch].w);
        }
    }

    // rotate + translate: out[j] = acc_x*R[0][j] + acc_y*R[1][j] + acc_z*R[2][j] + T[j]
    float o[4][3];
    const float ax[4] = {acc[0].x, acc[0].y, acc[0].z, acc[0].w};
    const float ay[4] = {acc[1].x, acc[1].y, acc[1].z, acc[1].w};
    const float az[4] = {acc[2].x, acc[2].y, acc[2].z, acc[2].w};
    #pragma unroll
    for (int e = 0; e < 4; e++)
        #pragma unroll
        for (int j = 0; j < 3; j++)
            o[e][j] = fmaf(ax[e], sR[0 * 3 + j],
                      fmaf(ay[e], sR[1 * 3 + j],
                      fmaf(az[e], sR[2 * 3 + j], sT[j])));

    // 12 consecutive floats starting at feat + v*6144 + q*12  (48B, 16B-aligned)
    float4* out = (float4*)(feat + (size_t)v * MAX_SIFT * 3) + (size_t)q * 3;
    out[0] = make_float4(o[0][0], o[0][1], o[0][2], o[1][0]);
    out[1] = make_float4(o[1][1], o[1][2], o[2][0], o[2][1]);
    out[2] = make_float4(o[2][2], o[3][0], o[3][1], o[3][2]);
}

// ---------------------------------------------------------------------------
// Kernel 3: delta[t] = || feat_flat[m0] - feat_flat[m1] ||
// matches is int32 (JAX x64 disabled silently downcasts jnp.int64 -> int32).
// Indices masked into range defensively: if the dtype theory is wrong this
// produces a diagnosable rel_err instead of an illegal access.
// feat (12 MiB) is L2-resident right after kernel 2.
// ---------------------------------------------------------------------------
__global__ void __launch_bounds__(256)
delta_kernel(const int* __restrict__ matches,   // (1e6, 2) int32
             const float* __restrict__ feat,
             float* __restrict__ delta)
{
    const int t = blockIdx.x * blockDim.x + threadIdx.x;
    if (t >= N_MATCHES) return;

    int2 m = ((const int2*)matches)[t];
    unsigned i0 = (unsigned)m.x % FLAT_ROWS;
    unsigned i1 = (unsigned)m.y % FLAT_ROWS;
    const float* p0 = feat + (size_t)i0 * 3;
    const float* p1 = feat + (size_t)i1 * 3;
    float dx = __ldg(p0 + 0) - __ldg(p1 + 0);
    float dy = __ldg(p0 + 1) - __ldg(p1 + 1);
    float dz = __ldg(p0 + 2) - __ldg(p1 + 2);
    delta[t] = sqrtf(fmaf(dx, dx, fmaf(dy, dy, dz * dz)));
}

// ---------------------------------------------------------------------------
extern "C" void kernel_launch(void* const* d_in, const int* in_sizes, int n_in,
                              void* d_out, int out_size)
{
    const float* euler   = (const float*)d_in[0];   // c33_euler (512,3)
    const float* c_3     = (const float*)d_in[1];   // (512,1,3)
    const float* beta    = (const float*)d_in[2];   // (512,1,1,32)
    const float* pdepth  = (const float*)d_in[3];   // (512,3,32,2048)
    const float* pdepth0 = (const float*)d_in[4];   // (512,3,1,2048)
    const int*   matches = (const int*)d_in[5];     // (1e6,2) int32

    float* feat  = (float*)d_out;              // first 3,145,728 floats
    float* delta = feat + FEAT_ELEMS;          // next 1,000,000 floats

    scan_kernel<<<1, N_VIEWS>>>(euler, c_3);
    feat_kernel<<<N_VIEWS, 512>>>(beta, pdepth, pdepth0, feat);
    delta_kernel<<<(N_MATCHES + 255) / 256, 256>>>(matches, feat, delta);
}

// round 5
// speedup vs baseline: 1.0755x; 1.0755x over previous
#include <cuda_runtime.h>
#include <cuda_bf16.h>
#include <math.h>

#define N_VIEWS   512
#define N_MULTI   32
#define MAX_SIFT  2048
#define N_MATCHES 1000000

#define FEAT_ELEMS (N_VIEWS * MAX_SIFT * 3)   // 3,145,728
#define FLAT_ROWS  (N_VIEWS * MAX_SIFT)       // 1,048,576

// Per-view cumulative rotation (row-major 3x3) and translation.
__device__ float g_c33[N_VIEWS * 9];
__device__ float g_c3[N_VIEWS * 3];

// ---------------------------------------------------------------------------
// Kernel 1: rotations + prefix matmul scan + cumsum(c_3).
// Two-level scan: warp-level Kogge-Stone via shuffles (no block syncs),
// then warp-0 scan of the 16 warp aggregates, then combine.
// One block of 512 threads (one thread per view).
// ---------------------------------------------------------------------------
__device__ __forceinline__ void mat33_mul(const float* __restrict__ A,
                                          const float* __restrict__ B,
                                          float* __restrict__ C)
{
    // C = A @ B, row-major
    #pragma unroll
    for (int r = 0; r < 3; r++)
        #pragma unroll
        for (int c = 0; c < 3; c++)
            C[r * 3 + c] = fmaf(A[r * 3 + 0], B[0 * 3 + c],
                           fmaf(A[r * 3 + 1], B[1 * 3 + c],
                                A[r * 3 + 2] * B[2 * 3 + c]));
}

__global__ void __launch_bounds__(512)
scan_kernel(const float* __restrict__ euler,   // (512,3)
            const float* __restrict__ c_3)     // (512,1,3)
{
    const int i    = threadIdx.x;     // view index
    const int lane = i & 31;
    const int warp = i >> 5;          // 0..15

    // Build rotation from Tait-Bryan angles
    float a = euler[i * 3 + 0];
    float b = euler[i * 3 + 1];
    float c = euler[i * 3 + 2];
    float sa, ca, sb, cb, sc, cc;
    sincosf(a, &sa, &ca);
    sincosf(b, &sb, &cb);
    sincosf(c, &sc, &cc);

    float M[9], T[3];
    M[0] = ca * cc + sa * sb * sc;
    M[1] = -sa * cb;
    M[2] = -ca * sc + sa * sb * cc;
    M[3] = sa * cc - ca * sb * sc;
    M[4] = ca * cb;
    M[5] = -sa * sc - ca * sb * cc;
    M[6] = cb * sc;
    M[7] = sb;
    M[8] = cb * cc;
    T[0] = c_3[i * 3 + 0];
    T[1] = c_3[i * 3 + 1];
    T[2] = c_3[i * 3 + 2];

    // Phase 1: inclusive Kogge-Stone scan within each warp (earlier on left)
    #pragma unroll
    for (int d = 1; d < 32; d <<= 1) {
        float A[9], t0, t1, t2;
        #pragma unroll
        for (int k = 0; k < 9; k++) A[k] = __shfl_up_sync(0xffffffffu, M[k], d);
        t0 = __shfl_up_sync(0xffffffffu, T[0], d);
        t1 = __shfl_up_sync(0xffffffffu, T[1], d);
        t2 = __shfl_up_sync(0xffffffffu, T[2], d);
        if (lane >= d) {
            float C[9];
            mat33_mul(A, M, C);
            #pragma unroll
            for (int k = 0; k < 9; k++) M[k] = C[k];
            T[0] += t0; T[1] += t1; T[2] += t2;
        }
    }

    // Phase 2: warp 0 scans the 16 warp aggregates
    __shared__ float aggM[16][9];
    __shared__ float aggT[16][3];
    if (lane == 31) {
        #pragma unroll
        for (int k = 0; k < 9; k++) aggM[warp][k] = M[k];
        aggT[warp][0] = T[0]; aggT[warp][1] = T[1]; aggT[warp][2] = T[2];
    }
    __syncthreads();

    if (warp == 0) {
        float Ma[9] = {1.f, 0.f, 0.f, 0.f, 1.f, 0.f, 0.f, 0.f, 1.f};
        float Ta[3] = {0.f, 0.f, 0.f};
        if (lane < 16) {
            #pragma unroll
            for (int k = 0; k < 9; k++) Ma[k] = aggM[lane][k];
            Ta[0] = aggT[lane][0]; Ta[1] = aggT[lane][1]; Ta[2] = aggT[lane][2];
        }
        #pragma unroll
        for (int d = 1; d < 16; d <<= 1) {
            float A[9], t0, t1, t2;
            #pragma unroll
            for (int k = 0; k < 9; k++) A[k] = __shfl_up_sync(0xffffffffu, Ma[k], d);
            t0 = __shfl_up_sync(0xffffffffu, Ta[0], d);
            t1 = __shfl_up_sync(0xffffffffu, Ta[1], d);
            t2 = __shfl_up_sync(0xffffffffu, Ta[2], d);
            if (lane >= d && lane < 16) {
                float C[9];
                mat33_mul(A, Ma, C);
                #pragma unroll
                for (int k = 0; k < 9; k++) Ma[k] = C[k];
                Ta[0] += t0; Ta[1] += t1; Ta[2] += t2;
            }
        }
        if (lane < 16) {
            #pragma unroll
            for (int k = 0; k < 9; k++) aggM[lane][k] = Ma[k];
            aggT[lane][0] = Ta[0]; aggT[lane][1] = Ta[1]; aggT[lane][2] = Ta[2];
        }
    }
    __syncthreads();

    // Phase 3: combine — prefix of warps 0..w-1 applied on the left
    if (warp > 0) {
        float P[9], C[9];
        #pragma unroll
        for (int k = 0; k < 9; k++) P[k] = aggM[warp - 1][k];
        mat33_mul(P, M, C);
        #pragma unroll
        for (int k = 0; k < 9; k++) M[k] = C[k];
        T[0] += aggT[warp - 1][0];
        T[1] += aggT[warp - 1][1];
        T[2] += aggT[warp - 1][2];
    }

    #pragma unroll
    for (int k = 0; k < 9; k++) g_c33[i * 9 + k] = M[k];
    g_c3[i * 3 + 0] = T[0];
    g_c3[i * 3 + 1] = T[1];
    g_c3[i * 3 + 2] = T[2];
}

// ---------------------------------------------------------------------------
// Kernel 2: feat[v,s,:] = (sum_m beta[v,m]*pdepth[v,:,m,s] + pdepth0[v,:,s]) @ c33[v] + c3[v]
// Grid = 4 blocks per view x 128 threads; each thread owns one float4 column.
// Streaming inputs use __ldcs (evict-first) to keep feat resident in L2 for
// the delta gather.
// ---------------------------------------------------------------------------
__global__ void __launch_bounds__(128)
feat_kernel(const float* __restrict__ beta,      // (512,1,1,32)
            const float* __restrict__ pdepth,    // (512,3,32,2048)
            const float* __restrict__ pdepth0,   // (512,3,1,2048)
            float* __restrict__ feat)            // (512,2048,3)
{
    const int v     = blockIdx.x >> 2;
    const int chunk = blockIdx.x & 3;
    const int q     = chunk * 128 + threadIdx.x;   // quad index within view

    __shared__ float sb[N_MULTI];
    __shared__ float sR[9];
    __shared__ float sT[3];

    if (threadIdx.x < N_MULTI) sb[threadIdx.x] = beta[v * N_MULTI + threadIdx.x];
    if (threadIdx.x >= 32 && threadIdx.x < 41) sR[threadIdx.x - 32] = g_c33[v * 9 + (threadIdx.x - 32)];
    if (threadIdx.x >= 64 && threadIdx.x < 67) sT[threadIdx.x - 64] = g_c3[v * 3 + (threadIdx.x - 64)];
    __syncthreads();

    // accumulators per channel (x,y,z), 4 sifts wide
    const float4* p0 = (const float4*)(pdepth0 + (size_t)v * 3 * MAX_SIFT);
    float4 acc[3];
    #pragma unroll
    for (int ch = 0; ch < 3; ch++)
        acc[ch] = __ldcs(&p0[(size_t)ch * (MAX_SIFT / 4) + q]);

    const float4* pd = (const float4*)(pdepth + (size_t)v * 3 * N_MULTI * MAX_SIFT);
    #pragma unroll
    for (int m = 0; m < N_MULTI; m++) {
        float bm = sb[m];
        #pragma unroll
        for (int ch = 0; ch < 3; ch++) {
            float4 p = __ldcs(&pd[((size_t)ch * N_MULTI + m) * (MAX_SIFT / 4) + q]);
            acc[ch].x = fmaf(bm, p.x, acc[ch].x);
            acc[ch].y = fmaf(bm, p.y, acc[ch].y);
            acc[ch].z = fmaf(bm, p.z, acc[ch].z);
            acc[ch].w = fmaf(bm, p.w, acc[ch].w);
        }
    }

    // rotate + translate
    float o[4][3];
    const float ax[4] = {acc[0].x, acc[0].y, acc[0].z, acc[0].w};
    const float ay[4] = {acc[1].x, acc[1].y, acc[1].z, acc[1].w};
    const float az[4] = {acc[2].x, acc[2].y, acc[2].z, acc[2].w};
    #pragma unroll
    for (int e = 0; e < 4; e++)
        #pragma unroll
        for (int j = 0; j < 3; j++)
            o[e][j] = fmaf(ax[e], sR[0 * 3 + j],
                      fmaf(ay[e], sR[1 * 3 + j],
                      fmaf(az[e], sR[2 * 3 + j], sT[j])));

    // 12 consecutive floats at feat + v*6144 + q*12 (48B, 16B-aligned)
    float4* out = (float4*)(feat + (size_t)v * MAX_SIFT * 3) + (size_t)q * 3;
    out[0] = make_float4(o[0][0], o[0][1], o[0][2], o[1][0]);
    out[1] = make_float4(o[1][1], o[1][2], o[2][0], o[2][1]);
    out[2] = make_float4(o[2][2], o[3][0], o[3][1], o[3][2]);
}

// ---------------------------------------------------------------------------
// Kernel 3: delta[t] = || feat_flat[m0] - feat_flat[m1] ||
// matches is int32 (JAX x64-disabled downcast). feat is L2-resident.
// ---------------------------------------------------------------------------
__global__ void __launch_bounds__(256)
delta_kernel(const int* __restrict__ matches,   // (1e6, 2) int32
             const float* __restrict__ feat,
             float* __restrict__ delta)
{
    const int t = blockIdx.x * blockDim.x + threadIdx.x;
    if (t >= N_MATCHES) return;

    int2 m = ((const int2*)matches)[t];
    unsigned i0 = (unsigned)m.x % FLAT_ROWS;
    unsigned i1 = (unsigned)m.y % FLAT_ROWS;
    const float* p0 = feat + (size_t)i0 * 3;
    const float* p1 = feat + (size_t)i1 * 3;
    float dx = __ldg(p0 + 0) - __ldg(p1 + 0);
    float dy = __ldg(p0 + 1) - __ldg(p1 + 1);
    float dz = __ldg(p0 + 2) - __ldg(p1 + 2);
    delta[t] = sqrtf(fmaf(dx, dx, fmaf(dy, dy, dz * dz)));
}

// ---------------------------------------------------------------------------
extern "C" void kernel_launch(void* const* d_in, const int* in_sizes, int n_in,
                              void* d_out, int out_size)
{
    const float* euler   = (const float*)d_in[0];   // c33_euler (512,3)
    const float* c_3     = (const float*)d_in[1];   // (512,1,3)
    const float* beta    = (const float*)d_in[2];   // (512,1,1,32)
    const float* pdepth  = (const float*)d_in[3];   // (512,3,32,2048)
    const float* pdepth0 = (const float*)d_in[4];   // (512,3,1,2048)
    const int*   matches = (const int*)d_in[5];     // (1e6,2) int32

    float* feat  = (float*)d_out;              // first 3,145,728 floats
    float* delta = feat + FEAT_ELEMS;          // next 1,000,000 floats

    scan_kernel<<<1, N_VIEWS>>>(euler, c_3);
    feat_kernel<<<N_VIEWS * 4, 128>>>(beta, pdepth, pdepth0, feat);
    delta_kernel<<<(N_MATCHES + 255) / 256, 256>>>(matches, feat, delta);
}